// round 1
// baseline (speedup 1.0000x reference)
#include <cuda_runtime.h>
#include <math.h>

// Problem constants (fixed by the dataset)
#define L_LAYERS 16
#define QD 2048
#define BATCH 4096

// Scratch: ping-pong state buffers + per-layer scales (allocation-free rule:
// __device__ globals only).
__device__ float g_state0[BATCH * QD];
__device__ float g_state1[BATCH * QD];
__device__ float g_scales[L_LAYERS * QD];

// ---------------------------------------------------------------------------
// scales[l, d] = cos(a0/2) * cos(a1/2) * cos(a2/2)
// ---------------------------------------------------------------------------
__global__ void compute_scales_kernel(const float* __restrict__ angles) {
    int idx = blockIdx.x * blockDim.x + threadIdx.x;
    if (idx < L_LAYERS * QD) {
        const float* a = angles + idx * 3;
        g_scales[idx] = cosf(0.5f * a[0]) * cosf(0.5f * a[1]) * cosf(0.5f * a[2]);
    }
}

// ---------------------------------------------------------------------------
// C[M,N] = (A[M,K] ⊙ scale[K broadcast over rows]) @ W[K,N]
// Classic 128x128x8 register-tiled SGEMM, 256 threads, 8x8 per-thread tile.
// M=4096, N=2048, K=2048 — all dims divisible by tile sizes, no bounds checks.
// ---------------------------------------------------------------------------
#define BM 128
#define BN 128
#define BK 8
#define TM 8
#define TN 8

template <bool USE_SCALE>
__global__ __launch_bounds__(256, 2)
void sgemm_scaled_kernel(const float* __restrict__ A,
                         const float* __restrict__ scale,  // [K] or unused
                         const float* __restrict__ W,
                         float* __restrict__ C,
                         int M, int N, int K) {
    __shared__ float As[BK][BM];   // transposed A tile
    __shared__ float Bs[BK][BN];

    const int tid = threadIdx.x;        // 0..255
    const int tx = tid & 15;            // 0..15 (cols)
    const int ty = tid >> 4;            // 0..15 (rows)

    const int blockRow = blockIdx.y * BM;
    const int blockCol = blockIdx.x * BN;

    // A-tile load mapping: 128 rows x 8 cols = 1024 floats = 256 threads x float4
    const int aRow  = tid >> 1;          // 0..127
    const int aCol4 = (tid & 1) << 2;    // 0 or 4

    // B-tile load mapping: 8 rows x 128 cols = 1024 floats = 256 threads x float4
    const int bRow  = tid >> 5;          // 0..7
    const int bCol4 = (tid & 31) << 2;   // 0..124 step 4

    float acc[TM][TN];
#pragma unroll
    for (int i = 0; i < TM; i++)
#pragma unroll
        for (int j = 0; j < TN; j++)
            acc[i][j] = 0.0f;

    const float* Aptr = A + (size_t)(blockRow + aRow) * K + aCol4;
    const float* Wptr = W + (size_t)bRow * N + blockCol + bCol4;

    for (int k0 = 0; k0 < K; k0 += BK) {
        // Load + (optionally) scale A tile, store transposed
        float4 a4 = *reinterpret_cast<const float4*>(Aptr + k0);
        if (USE_SCALE) {
            float4 s4 = *reinterpret_cast<const float4*>(scale + k0 + aCol4);
            a4.x *= s4.x; a4.y *= s4.y; a4.z *= s4.z; a4.w *= s4.w;
        }
        As[aCol4 + 0][aRow] = a4.x;
        As[aCol4 + 1][aRow] = a4.y;
        As[aCol4 + 2][aRow] = a4.z;
        As[aCol4 + 3][aRow] = a4.w;

        // Load W tile
        float4 b4 = *reinterpret_cast<const float4*>(Wptr + (size_t)k0 * N);
        *reinterpret_cast<float4*>(&Bs[bRow][bCol4]) = b4;

        __syncthreads();

#pragma unroll
        for (int kk = 0; kk < BK; kk++) {
            float ra[TM], rb[TN];
#pragma unroll
            for (int i = 0; i < TM; i++) ra[i] = As[kk][ty * TM + i];
#pragma unroll
            for (int j = 0; j < TN; j++) rb[j] = Bs[kk][tx * TN + j];
#pragma unroll
            for (int i = 0; i < TM; i++)
#pragma unroll
                for (int j = 0; j < TN; j++)
                    acc[i][j] = fmaf(ra[i], rb[j], acc[i][j]);
        }
        __syncthreads();
    }

    // Epilogue: float4 stores
#pragma unroll
    for (int i = 0; i < TM; i++) {
        float* crow = C + (size_t)(blockRow + ty * TM + i) * N + blockCol + tx * TN;
        float4 v0 = make_float4(acc[i][0], acc[i][1], acc[i][2], acc[i][3]);
        float4 v1 = make_float4(acc[i][4], acc[i][5], acc[i][6], acc[i][7]);
        *reinterpret_cast<float4*>(crow + 0) = v0;
        *reinterpret_cast<float4*>(crow + 4) = v1;
    }
}

// ---------------------------------------------------------------------------
// Launch: scales, 16 scaled layer GEMMs (ping-pong), final measurement GEMM.
// ---------------------------------------------------------------------------
extern "C" void kernel_launch(void* const* d_in, const int* in_sizes, int n_in,
                              void* d_out, int out_size) {
    const float* input_state = (const float*)d_in[0];  // [B, QD]
    const float* angles      = (const float*)d_in[1];  // [L, QD, 3]
    const float* weights     = (const float*)d_in[2];  // [L, QD, QD]
    const float* meas_basis  = (const float*)d_in[3];  // [QD, QD]
    float* out = (float*)d_out;                        // [B, QD]

    (void)in_sizes; (void)n_in; (void)out_size;

    float* s0; float* s1; float* sc;
    cudaGetSymbolAddress((void**)&s0, g_state0);
    cudaGetSymbolAddress((void**)&s1, g_state1);
    cudaGetSymbolAddress((void**)&sc, g_scales);

    compute_scales_kernel<<<(L_LAYERS * QD + 255) / 256, 256>>>(angles);

    dim3 grid(QD / BN, BATCH / BM);  // (16, 32)
    dim3 block(256);

    const float* cur = input_state;
    for (int l = 0; l < L_LAYERS; l++) {
        float* dst = (l & 1) ? s1 : s0;
        sgemm_scaled_kernel<true><<<grid, block>>>(
            cur, sc + l * QD, weights + (size_t)l * QD * QD, dst,
            BATCH, QD, QD);
        cur = dst;
    }

    // Final: out = state @ measurement_basis (no scale)
    sgemm_scaled_kernel<false><<<grid, block>>>(
        cur, nullptr, meas_basis, out, BATCH, QD, QD);
}

// round 3
// speedup vs baseline: 10.7088x; 10.7088x over previous
#include <cuda_runtime.h>
#include <cuda_bf16.h>
#include <cstdint>
#include <math.h>

#define L_LAYERS 16
#define QD 2048
#define BATCH 4096
#define NMAT 17  // 16 layers + measurement basis

// tcgen05 is only available on arch-specific targets (sm_103a), not the
// generic compute_103 PTX pass the harness also emits. Gate all tcgen05 asm.
#if defined(__CUDA_ARCH_FEAT_SM103_ALL) || defined(__CUDA_ARCH_FEAT_SM100_ALL) || \
    (defined(__CUDA_ARCH_SPECIFIC__) && (__CUDA_ARCH_SPECIFIC__ >= 1000))
#define HAS_TCGEN05 1
#else
#define HAS_TCGEN05 0
#endif

// ---------------------------------------------------------------------------
// Device scratch (allocation-free rule: __device__ globals)
// ---------------------------------------------------------------------------
__device__ __nv_bfloat16 g_Wt_hi[NMAT][QD][QD];  // [mat][n][k]  (W transposed)
__device__ __nv_bfloat16 g_Wt_lo[NMAT][QD][QD];
__device__ __nv_bfloat16 g_A_hi[2][BATCH][QD];   // ping-pong state, bf16 hi
__device__ __nv_bfloat16 g_A_lo[2][BATCH][QD];   // ping-pong state, bf16 lo
__device__ float g_scales[L_LAYERS][QD];

// ---------------------------------------------------------------------------
// PTX helpers
// ---------------------------------------------------------------------------
__device__ __forceinline__ uint32_t smem_u32(const void* p) {
    uint32_t a;
    asm("{ .reg .u64 t; cvta.to.shared.u64 t, %1; cvt.u32.u64 %0, t; }"
        : "=r"(a) : "l"(p));
    return a;
}

__device__ __forceinline__ uint32_t elect_one_pred() {
    uint32_t pred;
    asm volatile(
        "{\n\t.reg .pred p;\n\telect.sync _|p, 0xFFFFFFFF;\n\t"
        "selp.b32 %0, 1, 0, p;\n\t}"
        : "=r"(pred));
    return pred;
}

#define MBARRIER_INIT(addr, count) \
    asm volatile("mbarrier.init.shared.b64 [%0], %1;" \
                 :: "r"((uint32_t)(addr)), "r"((uint32_t)(count)) : "memory")

#define MBARRIER_WAIT_PARITY(mbar_smem_addr, phase_parity) do { \
    uint32_t _mbar = (uint32_t)(mbar_smem_addr); \
    uint32_t _parity = (uint32_t)(phase_parity); \
    uint32_t _done; \
    asm volatile( \
        "{\n\t.reg .pred p;\n\t" \
        "mbarrier.try_wait.parity.acquire.cta.shared::cta.b64 p, [%1], %2;\n\t" \
        "selp.b32 %0, 1, 0, p;\n\t}" \
        : "=r"(_done) : "r"(_mbar), "r"(_parity) : "memory"); \
    if (!_done) { \
        asm volatile( \
            "{\n\t.reg .pred P1;\n\t" \
            "WAIT_LOOP_%=:\n\t" \
            "mbarrier.try_wait.parity.acquire.cta.shared::cta.b64 P1, [%0], %1, 0x989680;\n\t" \
            "@P1 bra.uni WAIT_DONE_%=;\n\t" \
            "bra.uni WAIT_LOOP_%=;\n\t" \
            "WAIT_DONE_%=:\n\t}" \
            :: "r"(_mbar), "r"(_parity) : "memory"); \
    } \
} while (0)

__device__ __forceinline__ void cp_async16(uint32_t dst, const void* src) {
    asm volatile("cp.async.cg.shared.global [%0], [%1], 16;"
                 :: "r"(dst), "l"(src));
}
__device__ __forceinline__ void cp_async_arrive_noinc(uint32_t mbar) {
    asm volatile("cp.async.mbarrier.arrive.noinc.shared::cta.b64 [%0];"
                 :: "r"(mbar) : "memory");
}

#define FENCE_PROXY_ASYNC() \
    asm volatile("fence.proxy.async.shared::cta;" ::: "memory")

#if HAS_TCGEN05
#define TCGEN05_ALLOC(smem_result_addr, nCols) \
    asm volatile("tcgen05.alloc.cta_group::1.sync.aligned.shared::cta.b32 [%0], %1;" \
                 :: "r"((uint32_t)(smem_result_addr)), "r"((uint32_t)(nCols)) : "memory")
#define TCGEN05_DEALLOC(tmem_addr, nCols) \
    asm volatile("tcgen05.dealloc.cta_group::1.sync.aligned.b32 %0, %1;" \
                 :: "r"(tmem_addr), "r"((uint32_t)(nCols)))
#define TCGEN05_RELINQUISH() \
    asm volatile("tcgen05.relinquish_alloc_permit.cta_group::1.sync.aligned;")
#define TCGEN05_COMMIT(mbar) \
    asm volatile("tcgen05.commit.cta_group::1.mbarrier::arrive::one.shared::cluster.b64 [%0];" \
                 :: "r"((uint32_t)(mbar)) : "memory")
#define TCGEN05_FENCE_AFTER() \
    asm volatile("tcgen05.fence::after_thread_sync;" ::: "memory")
#define TCGEN05_FENCE_BEFORE() \
    asm volatile("tcgen05.fence::before_thread_sync;" ::: "memory")
#define TCGEN05_WAIT_LD() \
    asm volatile("tcgen05.wait::ld.sync.aligned;" ::: "memory")

#define TCGEN05_LD_32X32B_X32(r, tmem_addr) \
    asm volatile( \
        "tcgen05.ld.sync.aligned.32x32b.x32.b32 " \
        "{%0, %1, %2, %3, %4, %5, %6, %7, " \
        " %8, %9, %10, %11, %12, %13, %14, %15, " \
        " %16, %17, %18, %19, %20, %21, %22, %23, " \
        " %24, %25, %26, %27, %28, %29, %30, %31}, [%32];" \
        : "=r"((r)[0]),  "=r"((r)[1]),  "=r"((r)[2]),  "=r"((r)[3]), \
          "=r"((r)[4]),  "=r"((r)[5]),  "=r"((r)[6]),  "=r"((r)[7]), \
          "=r"((r)[8]),  "=r"((r)[9]),  "=r"((r)[10]), "=r"((r)[11]), \
          "=r"((r)[12]), "=r"((r)[13]), "=r"((r)[14]), "=r"((r)[15]), \
          "=r"((r)[16]), "=r"((r)[17]), "=r"((r)[18]), "=r"((r)[19]), \
          "=r"((r)[20]), "=r"((r)[21]), "=r"((r)[22]), "=r"((r)[23]), \
          "=r"((r)[24]), "=r"((r)[25]), "=r"((r)[26]), "=r"((r)[27]), \
          "=r"((r)[28]), "=r"((r)[29]), "=r"((r)[30]), "=r"((r)[31]) \
        : "r"(tmem_addr))

// SS-mode bf16 MMA, cg1
__device__ __forceinline__ void mma_f16_ss(uint32_t d, uint64_t da, uint64_t db,
                                           uint32_t idesc, uint32_t en) {
    asm volatile(
        "{\n\t.reg .pred p;\n\tsetp.ne.u32 p, %4, 0;\n\t"
        "tcgen05.mma.cta_group::1.kind::f16 [%0], %1, %2, %3, {%5,%5,%5,%5}, p;\n\t}"
        :: "r"(d), "l"(da), "l"(db), "r"(idesc), "r"(en), "r"(0u) : "memory");
}
#endif  // HAS_TCGEN05

// SW128 smem matrix descriptor (K-major, version=1, LBO=1, SBO=64)
static constexpr uint64_t SMEM_DESC_BASE_SW128 =
    (uint64_t(2)  << 61) | (uint64_t(1) << 46) | (uint64_t(64) << 32) | (uint64_t(1) << 16);
#define MAKE_SMEM_DESC(base_addr) \
    (SMEM_DESC_BASE_SW128 | ((uint64_t)((base_addr) >> 4) & 0x3FFF))

__device__ __forceinline__ uint32_t swz128(uint32_t o) {
    return o ^ ((o >> 3) & 0x70);
}

// ---------------------------------------------------------------------------
// Small prep kernels
// ---------------------------------------------------------------------------
__global__ void compute_scales_kernel(const float* __restrict__ angles) {
    int idx = blockIdx.x * blockDim.x + threadIdx.x;
    if (idx < L_LAYERS * QD) {
        const float* a = angles + idx * 3;
        (&g_scales[0][0])[idx] = cosf(0.5f * a[0]) * cosf(0.5f * a[1]) * cosf(0.5f * a[2]);
    }
}

// Transpose + bf16 hi/lo split of the 17 weight matrices: Wt[n][k] = W[k][n]
__global__ void convert_weights_kernel(const float* __restrict__ weights,
                                       const float* __restrict__ meas) {
    __shared__ float tile[32][33];
    const int m = blockIdx.z;
    const float* src = (m < L_LAYERS) ? (weights + (size_t)m * QD * QD) : meas;
    const int k0 = blockIdx.x * 32, n0 = blockIdx.y * 32;
    const int tx = threadIdx.x, ty = threadIdx.y;  // 32 x 8
#pragma unroll
    for (int i = 0; i < 32; i += 8)
        tile[ty + i][tx] = src[(size_t)(k0 + ty + i) * QD + n0 + tx];
    __syncthreads();
    __nv_bfloat16* dh = &g_Wt_hi[m][0][0];
    __nv_bfloat16* dl = &g_Wt_lo[m][0][0];
#pragma unroll
    for (int i = 0; i < 32; i += 8) {
        float x = tile[tx][ty + i];
        __nv_bfloat16 h = __float2bfloat16(x);
        __nv_bfloat16 l = __float2bfloat16(x - __bfloat162float(h));
        size_t o = (size_t)(n0 + ty + i) * QD + k0 + tx;
        dh[o] = h;
        dl[o] = l;
    }
}

// input_state * scale[0] -> bf16 hi/lo into state set 0
__global__ void convert_input_kernel(const float* __restrict__ in) {
    int idx = blockIdx.x * blockDim.x + threadIdx.x;  // 4 elems each
    int base = idx << 2;
    float4 v = *(const float4*)(in + base);
    int k = base & (QD - 1);
    const float4 s = *(const float4*)(&g_scales[0][k]);
    float x0 = v.x * s.x, x1 = v.y * s.y, x2 = v.z * s.z, x3 = v.w * s.w;
    __nv_bfloat16 h0 = __float2bfloat16(x0), h1 = __float2bfloat16(x1);
    __nv_bfloat16 h2 = __float2bfloat16(x2), h3 = __float2bfloat16(x3);
    __nv_bfloat16 l0 = __float2bfloat16(x0 - __bfloat162float(h0));
    __nv_bfloat16 l1 = __float2bfloat16(x1 - __bfloat162float(h1));
    __nv_bfloat16 l2 = __float2bfloat16(x2 - __bfloat162float(h2));
    __nv_bfloat16 l3 = __float2bfloat16(x3 - __bfloat162float(h3));
    uint32_t hp0 = (uint32_t)__bfloat16_as_ushort(h0) | ((uint32_t)__bfloat16_as_ushort(h1) << 16);
    uint32_t hp1 = (uint32_t)__bfloat16_as_ushort(h2) | ((uint32_t)__bfloat16_as_ushort(h3) << 16);
    uint32_t lp0 = (uint32_t)__bfloat16_as_ushort(l0) | ((uint32_t)__bfloat16_as_ushort(l1) << 16);
    uint32_t lp1 = (uint32_t)__bfloat16_as_ushort(l2) | ((uint32_t)__bfloat16_as_ushort(l3) << 16);
    *(uint2*)(&g_A_hi[0][0][0] + base) = make_uint2(hp0, hp1);
    *(uint2*)(&g_A_lo[0][0][0] + base) = make_uint2(lp0, lp1);
}

// ---------------------------------------------------------------------------
// tcgen05 GEMM: D[128x256] fp32 = (Ahi+Alo)[128,K] x (Bhi+Blo)[256,K]^T
// (3-term split, lo*lo dropped).  Warps 0-7 = cp.async producers + epilogue,
// warp 8 = MMA issuer.  2-stage smem pipeline (96 KB/stage), K-stage = 64.
// mode: 0 = write (acc*scaleNext) as bf16 hi/lo, 1 = bf16 hi/lo unscaled,
//       2 = fp32 to out.
// ---------------------------------------------------------------------------
#define BM 128
#define BN 256
#define STAGES 2
#define A_TILE_B (BM * 128)              // 16 KB
#define B_TILE_B (BN * 128)              // 32 KB
#define STAGE_B  (2 * A_TILE_B + 2 * B_TILE_B)  // 96 KB
#define K_ITERS  (QD / 64)               // 32
// idesc: F32 acc, BF16 a/b, N=256, M=128
#define MMA_IDESC 0x8400490u

__global__ __launch_bounds__(288, 1)
void qgemm_kernel(const __nv_bfloat16* __restrict__ Ahi,
                  const __nv_bfloat16* __restrict__ Alo,
                  const __nv_bfloat16* __restrict__ Bhi,
                  const __nv_bfloat16* __restrict__ Blo,
                  float* __restrict__ outF,
                  __nv_bfloat16* __restrict__ outHi,
                  __nv_bfloat16* __restrict__ outLo,
                  const float* __restrict__ scaleNext,
                  int mode) {
#if HAS_TCGEN05
    extern __shared__ __align__(1024) char smem_dyn[];
    __shared__ __align__(8) unsigned long long s_bars[5];  // full0 full1 empty0 empty1 done
    __shared__ uint32_t s_tmem;

    const int tid = threadIdx.x;
    const int wid = tid >> 5;
    const int lid = tid & 31;

    uint32_t smem_base = (smem_u32(smem_dyn) + 1023u) & ~1023u;
    uint32_t bar_full[2], bar_empty[2], bar_done;
    bar_full[0]  = smem_u32(&s_bars[0]);
    bar_full[1]  = smem_u32(&s_bars[1]);
    bar_empty[0] = smem_u32(&s_bars[2]);
    bar_empty[1] = smem_u32(&s_bars[3]);
    bar_done     = smem_u32(&s_bars[4]);

    if (tid == 0) {
        MBARRIER_INIT(bar_full[0], 256);
        MBARRIER_INIT(bar_full[1], 256);
        MBARRIER_INIT(bar_empty[0], 1);
        MBARRIER_INIT(bar_empty[1], 1);
        MBARRIER_INIT(bar_done, 1);
    }
    if (wid == 8) {
        TCGEN05_ALLOC(smem_u32(&s_tmem), 256);
    }
    __syncthreads();
    const uint32_t tmem_d = s_tmem;

    const int blockN = blockIdx.x * BN;
    const int blockM = blockIdx.y * BM;

    if (wid < 8) {
        // ---- producers: 256 threads, 24 x 16B cp.async per stage ----
        const char* pAh = (const char*)(Ahi + (size_t)blockM * QD);
        const char* pAl = (const char*)(Alo + (size_t)blockM * QD);
        const char* pBh = (const char*)(Bhi + (size_t)blockN * QD);
        const char* pBl = (const char*)(Blo + (size_t)blockN * QD);
        for (int it = 0; it < K_ITERS; ++it) {
            const int s = it & 1;
            if (it >= 2) MBARRIER_WAIT_PARITY(bar_empty[s], ((it >> 1) + 1) & 1);
            const uint32_t stage = smem_base + s * STAGE_B;
            const uint32_t kb = (uint32_t)it * 128;  // K byte offset (64 bf16)
#pragma unroll
            for (int i = 0; i < 4; ++i) {  // A tiles: 1024 x 16B chunks each
                int c = tid + i * 256;
                int r = c >> 3, j = (c & 7) << 4;
                uint32_t sw = swz128((uint32_t)r * 128 + j);
                size_t src = (size_t)r * (QD * 2) + kb + j;
                cp_async16(stage + sw, pAh + src);
                cp_async16(stage + A_TILE_B + sw, pAl + src);
            }
#pragma unroll
            for (int i = 0; i < 8; ++i) {  // B tiles: 2048 x 16B chunks each
                int c = tid + i * 256;
                int r = c >> 3, j = (c & 7) << 4;
                uint32_t sw = swz128((uint32_t)r * 128 + j);
                size_t src = (size_t)r * (QD * 2) + kb + j;
                cp_async16(stage + 2 * A_TILE_B + sw, pBh + src);
                cp_async16(stage + 2 * A_TILE_B + B_TILE_B + sw, pBl + src);
            }
            cp_async_arrive_noinc(bar_full[s]);
        }
    } else {
        // ---- MMA warp ----
        int phase = 0;
        uint32_t en = 0;
        for (int it = 0; it < K_ITERS; ++it) {
            const int s = it & 1;
            MBARRIER_WAIT_PARITY(bar_full[s], phase);
            FENCE_PROXY_ASYNC();
            const uint32_t stage = smem_base + s * STAGE_B;
            if (elect_one_pred()) {
                uint64_t dAh = MAKE_SMEM_DESC(stage);
                uint64_t dAl = MAKE_SMEM_DESC(stage + A_TILE_B);
                uint64_t dBh = MAKE_SMEM_DESC(stage + 2 * A_TILE_B);
                uint64_t dBl = MAKE_SMEM_DESC(stage + 2 * A_TILE_B + B_TILE_B);
#pragma unroll
                for (int kk = 0; kk < 4; ++kk) {
                    mma_f16_ss(tmem_d, dAh + kk * 2, dBh + kk * 2, MMA_IDESC, en);
                    en = 1;
                }
#pragma unroll
                for (int kk = 0; kk < 4; ++kk)
                    mma_f16_ss(tmem_d, dAh + kk * 2, dBl + kk * 2, MMA_IDESC, 1);
#pragma unroll
                for (int kk = 0; kk < 4; ++kk)
                    mma_f16_ss(tmem_d, dAl + kk * 2, dBh + kk * 2, MMA_IDESC, 1);
                TCGEN05_COMMIT(bar_empty[s]);
            }
            if (s == 1) phase ^= 1;
        }
        if (elect_one_pred()) TCGEN05_COMMIT(bar_done);
    }

    __syncthreads();
    MBARRIER_WAIT_PARITY(bar_done, 0);
    TCGEN05_FENCE_AFTER();

    // ---- epilogue: warps 0-3 -> cols 0-127, warps 4-7 -> cols 128-255 ----
    if (wid < 8) {
        const int row = blockM + (wid & 3) * 32 + lid;
        const int colhalf = (wid >> 2) * 128;
#pragma unroll
        for (int ch = 0; ch < 4; ++ch) {
            uint32_t regs[32];
            TCGEN05_LD_32X32B_X32(regs, tmem_d + colhalf + ch * 32);
            TCGEN05_WAIT_LD();
            const int col = blockN + colhalf + ch * 32;
            if (mode == 2) {
                float* dst = outF + (size_t)row * QD + col;
#pragma unroll
                for (int g = 0; g < 8; ++g)
                    *(float4*)(dst + g * 4) = make_float4(
                        __uint_as_float(regs[g * 4 + 0]), __uint_as_float(regs[g * 4 + 1]),
                        __uint_as_float(regs[g * 4 + 2]), __uint_as_float(regs[g * 4 + 3]));
            } else {
                __nv_bfloat16* dsth = outHi + (size_t)row * QD + col;
                __nv_bfloat16* dstl = outLo + (size_t)row * QD + col;
#pragma unroll
                for (int g = 0; g < 4; ++g) {  // 8 cols per group
                    uint32_t hp[4], lp[4];
#pragma unroll
                    for (int q = 0; q < 4; ++q) {
                        int c0 = g * 8 + q * 2;
                        float v0 = __uint_as_float(regs[c0]);
                        float v1 = __uint_as_float(regs[c0 + 1]);
                        if (mode == 0) {
                            v0 *= scaleNext[col + c0];
                            v1 *= scaleNext[col + c0 + 1];
                        }
                        __nv_bfloat16 h0 = __float2bfloat16(v0);
                        __nv_bfloat16 h1 = __float2bfloat16(v1);
                        __nv_bfloat16 l0 = __float2bfloat16(v0 - __bfloat162float(h0));
                        __nv_bfloat16 l1 = __float2bfloat16(v1 - __bfloat162float(h1));
                        hp[q] = (uint32_t)__bfloat16_as_ushort(h0) |
                                ((uint32_t)__bfloat16_as_ushort(h1) << 16);
                        lp[q] = (uint32_t)__bfloat16_as_ushort(l0) |
                                ((uint32_t)__bfloat16_as_ushort(l1) << 16);
                    }
                    *(uint4*)(dsth + g * 8) = make_uint4(hp[0], hp[1], hp[2], hp[3]);
                    *(uint4*)(dstl + g * 8) = make_uint4(lp[0], lp[1], lp[2], lp[3]);
                }
            }
            TCGEN05_FENCE_BEFORE();
        }
    }

    __syncthreads();
    if (wid == 8) {
        TCGEN05_RELINQUISH();
        TCGEN05_DEALLOC(tmem_d, 256);
    }
#endif  // HAS_TCGEN05
}

// ---------------------------------------------------------------------------
// Launch
// ---------------------------------------------------------------------------
extern "C" void kernel_launch(void* const* d_in, const int* in_sizes, int n_in,
                              void* d_out, int out_size) {
    const float* input_state = (const float*)d_in[0];  // [B, QD]
    const float* angles      = (const float*)d_in[1];  // [L, QD, 3]
    const float* weights     = (const float*)d_in[2];  // [L, QD, QD]
    const float* meas_basis  = (const float*)d_in[3];  // [QD, QD]
    float* out = (float*)d_out;
    (void)in_sizes; (void)n_in; (void)out_size;

    __nv_bfloat16 *wh, *wl, *ah, *al;
    float* sc;
    cudaGetSymbolAddress((void**)&wh, g_Wt_hi);
    cudaGetSymbolAddress((void**)&wl, g_Wt_lo);
    cudaGetSymbolAddress((void**)&ah, g_A_hi);
    cudaGetSymbolAddress((void**)&al, g_A_lo);
    cudaGetSymbolAddress((void**)&sc, g_scales);

    cudaFuncSetAttribute(qgemm_kernel, cudaFuncAttributeMaxDynamicSharedMemorySize,
                         STAGES * STAGE_B + 1024);

    compute_scales_kernel<<<(L_LAYERS * QD + 255) / 256, 256>>>(angles);
    {
        dim3 g(QD / 32, QD / 32, NMAT);
        dim3 b(32, 8);
        convert_weights_kernel<<<g, b>>>(weights, meas_basis);
    }
    convert_input_kernel<<<(BATCH * QD / 4) / 256, 256>>>(input_state);

    dim3 grid(QD / BN, BATCH / BM);  // (8, 32)
    const size_t MATSZ = (size_t)QD * QD;
    const size_t STSZ = (size_t)BATCH * QD;
    const size_t dyn = STAGES * STAGE_B + 1024;

    for (int l = 0; l < L_LAYERS; ++l) {
        int rs = l & 1, ws = (l + 1) & 1;
        qgemm_kernel<<<grid, 288, dyn>>>(
            ah + (size_t)rs * STSZ, al + (size_t)rs * STSZ,
            wh + (size_t)l * MATSZ, wl + (size_t)l * MATSZ,
            nullptr,
            ah + (size_t)ws * STSZ, al + (size_t)ws * STSZ,
            (l < L_LAYERS - 1) ? (sc + (size_t)(l + 1) * QD) : nullptr,
            (l < L_LAYERS - 1) ? 0 : 1);
    }
    // final measurement GEMM -> fp32 out
    qgemm_kernel<<<grid, 288, dyn>>>(
        ah, al, wh + (size_t)16 * MATSZ, wl + (size_t)16 * MATSZ,
        out, nullptr, nullptr, nullptr, 2);
}

// round 4
// speedup vs baseline: 13.1005x; 1.2233x over previous
#include <cuda_runtime.h>
#include <cuda_bf16.h>
#include <cstdint>
#include <math.h>

#define L_LAYERS 16
#define QD 2048
#define BATCH 4096
#define NMAT 17  // 16 layers + measurement basis

// tcgen05 only exists on arch-specific targets (sm_103a); the harness also
// emits a generic compute_103 PTX pass, which must compile without it.
#if defined(__CUDA_ARCH_FEAT_SM103_ALL) || defined(__CUDA_ARCH_FEAT_SM100_ALL) || \
    (defined(__CUDA_ARCH_SPECIFIC__) && (__CUDA_ARCH_SPECIFIC__ >= 1000))
#define HAS_TCGEN05 1
#else
#define HAS_TCGEN05 0
#endif

// ---------------------------------------------------------------------------
// Device scratch (allocation-free rule: __device__ globals).
// All GEMM operands live in K-staged, SW64-pre-swizzled layout:
//   [K/32 stages][rows][32 bf16]   (each (stage,row) = one 64B swizzled row)
// so a CTA's per-stage tile (256 rows x 64B = 16KB) is CONTIGUOUS in gmem and
// can be fetched with a single cp.async.bulk, landing in smem exactly in the
// layout the SW64 MMA smem descriptor expects.
// ---------------------------------------------------------------------------
#define KSTAGES (QD / 32)  // 64
__device__ __nv_bfloat16 g_Wst_hi[(size_t)NMAT * KSTAGES * QD * 32];
__device__ __nv_bfloat16 g_Wst_lo[(size_t)NMAT * KSTAGES * QD * 32];
__device__ __nv_bfloat16 g_Ast_hi[2][(size_t)KSTAGES * BATCH * 32];
__device__ __nv_bfloat16 g_Ast_lo[2][(size_t)KSTAGES * BATCH * 32];
__device__ float g_scales[L_LAYERS][QD];

// ---------------------------------------------------------------------------
// PTX helpers
// ---------------------------------------------------------------------------
__device__ __forceinline__ uint32_t smem_u32(const void* p) {
    uint32_t a;
    asm("{ .reg .u64 t; cvta.to.shared.u64 t, %1; cvt.u32.u64 %0, t; }"
        : "=r"(a) : "l"(p));
    return a;
}

__device__ __forceinline__ uint32_t elect_one_pred() {
    uint32_t pred;
    asm volatile(
        "{\n\t.reg .pred p;\n\telect.sync _|p, 0xFFFFFFFF;\n\t"
        "selp.b32 %0, 1, 0, p;\n\t}"
        : "=r"(pred));
    return pred;
}

#define MBARRIER_INIT(addr, count) \
    asm volatile("mbarrier.init.shared.b64 [%0], %1;" \
                 :: "r"((uint32_t)(addr)), "r"((uint32_t)(count)) : "memory")

#define MBARRIER_EXPECT_TX(addr, tx) \
    asm volatile("mbarrier.arrive.expect_tx.shared.b64 _, [%0], %1;" \
                 :: "r"((uint32_t)(addr)), "r"((uint32_t)(tx)) : "memory")

#define MBARRIER_WAIT_PARITY(mbar_smem_addr, phase_parity) do { \
    uint32_t _mbar = (uint32_t)(mbar_smem_addr); \
    uint32_t _parity = (uint32_t)(phase_parity); \
    uint32_t _done; \
    asm volatile( \
        "{\n\t.reg .pred p;\n\t" \
        "mbarrier.try_wait.parity.acquire.cta.shared::cta.b64 p, [%1], %2;\n\t" \
        "selp.b32 %0, 1, 0, p;\n\t}" \
        : "=r"(_done) : "r"(_mbar), "r"(_parity) : "memory"); \
    if (!_done) { \
        asm volatile( \
            "{\n\t.reg .pred P1;\n\t" \
            "WAIT_LOOP_%=:\n\t" \
            "mbarrier.try_wait.parity.acquire.cta.shared::cta.b64 P1, [%0], %1, 0x989680;\n\t" \
            "@P1 bra.uni WAIT_DONE_%=;\n\t" \
            "bra.uni WAIT_LOOP_%=;\n\t" \
            "WAIT_DONE_%=:\n\t}" \
            :: "r"(_mbar), "r"(_parity) : "memory"); \
    } \
} while (0)

__device__ __forceinline__ void bulk_cp(uint32_t dst, const void* src,
                                        uint32_t bytes, uint32_t mbar) {
    asm volatile(
        "cp.async.bulk.shared::cta.global.mbarrier::complete_tx::bytes "
        "[%0], [%1], %2, [%3];"
        :: "r"(dst), "l"(src), "r"(bytes), "r"(mbar) : "memory");
}

#if HAS_TCGEN05
#define TCGEN05_ALLOC(smem_result_addr, nCols) \
    asm volatile("tcgen05.alloc.cta_group::1.sync.aligned.shared::cta.b32 [%0], %1;" \
                 :: "r"((uint32_t)(smem_result_addr)), "r"((uint32_t)(nCols)) : "memory")
#define TCGEN05_DEALLOC(tmem_addr, nCols) \
    asm volatile("tcgen05.dealloc.cta_group::1.sync.aligned.b32 %0, %1;" \
                 :: "r"(tmem_addr), "r"((uint32_t)(nCols)))
#define TCGEN05_RELINQUISH() \
    asm volatile("tcgen05.relinquish_alloc_permit.cta_group::1.sync.aligned;")
#define TCGEN05_COMMIT(mbar) \
    asm volatile("tcgen05.commit.cta_group::1.mbarrier::arrive::one.shared::cluster.b64 [%0];" \
                 :: "r"((uint32_t)(mbar)) : "memory")
#define TCGEN05_FENCE_AFTER() \
    asm volatile("tcgen05.fence::after_thread_sync;" ::: "memory")
#define TCGEN05_FENCE_BEFORE() \
    asm volatile("tcgen05.fence::before_thread_sync;" ::: "memory")
#define TCGEN05_WAIT_LD() \
    asm volatile("tcgen05.wait::ld.sync.aligned;" ::: "memory")

#define TCGEN05_LD_32X32B_X32(r, tmem_addr) \
    asm volatile( \
        "tcgen05.ld.sync.aligned.32x32b.x32.b32 " \
        "{%0, %1, %2, %3, %4, %5, %6, %7, " \
        " %8, %9, %10, %11, %12, %13, %14, %15, " \
        " %16, %17, %18, %19, %20, %21, %22, %23, " \
        " %24, %25, %26, %27, %28, %29, %30, %31}, [%32];" \
        : "=r"((r)[0]),  "=r"((r)[1]),  "=r"((r)[2]),  "=r"((r)[3]), \
          "=r"((r)[4]),  "=r"((r)[5]),  "=r"((r)[6]),  "=r"((r)[7]), \
          "=r"((r)[8]),  "=r"((r)[9]),  "=r"((r)[10]), "=r"((r)[11]), \
          "=r"((r)[12]), "=r"((r)[13]), "=r"((r)[14]), "=r"((r)[15]), \
          "=r"((r)[16]), "=r"((r)[17]), "=r"((r)[18]), "=r"((r)[19]), \
          "=r"((r)[20]), "=r"((r)[21]), "=r"((r)[22]), "=r"((r)[23]), \
          "=r"((r)[24]), "=r"((r)[25]), "=r"((r)[26]), "=r"((r)[27]), \
          "=r"((r)[28]), "=r"((r)[29]), "=r"((r)[30]), "=r"((r)[31]) \
        : "r"(tmem_addr))

// SS-mode bf16 MMA, cg1
__device__ __forceinline__ void mma_f16_ss(uint32_t d, uint64_t da, uint64_t db,
                                           uint32_t idesc, uint32_t en) {
    asm volatile(
        "{\n\t.reg .pred p;\n\tsetp.ne.u32 p, %4, 0;\n\t"
        "tcgen05.mma.cta_group::1.kind::f16 [%0], %1, %2, %3, {%5,%5,%5,%5}, p;\n\t}"
        :: "r"(d), "l"(da), "l"(db), "r"(idesc), "r"(en), "r"(0u) : "memory");
}
#endif  // HAS_TCGEN05

// SW64 smem matrix descriptor: layout=4 (SW64), version=1, SBO=32, LBO=1.
// Rows of 64B packed consecutively, Swizzle<2,4,3> on byte addresses.
static constexpr uint64_t DESC_SW64_BASE =
    (uint64_t(4) << 61) | (uint64_t(1) << 46) | (uint64_t(32) << 32) | (uint64_t(1) << 16);
#define MAKE_DESC64(a) (DESC_SW64_BASE | ((uint64_t)((a) >> 4) & 0x3FFF))

// ---------------------------------------------------------------------------
// Prep kernels. They write the staged layout with the SW64 swizzle already
// applied: row r, 16B-unit u goes to unit u ^ ((r>>1)&3).
// ---------------------------------------------------------------------------
__global__ void compute_scales_kernel(const float* __restrict__ angles) {
    int idx = blockIdx.x * blockDim.x + threadIdx.x;
    if (idx < L_LAYERS * QD) {
        const float* a = angles + idx * 3;
        (&g_scales[0][0])[idx] = cosf(0.5f * a[0]) * cosf(0.5f * a[1]) * cosf(0.5f * a[2]);
    }
}

// Weights: Wt[n][k] = W[k][n], split hi/lo, staged+swizzled.
// Warp handles (mat m, stage sK, rows n0..n0+31). Lane=n, loop j=k elem.
__global__ void convert_weights_staged(const float* __restrict__ weights,
                                       const float* __restrict__ meas) {
    __shared__ __nv_bfloat16 sh[8][1024];
    __shared__ __nv_bfloat16 sl[8][1024];
    const int m = blockIdx.z;
    const float* src = (m < L_LAYERS) ? (weights + (size_t)m * QD * QD) : meas;
    const int sK = blockIdx.x;                       // 0..63
    const int w = threadIdx.x >> 5, ln = threadIdx.x & 31;
    const int n0 = (blockIdx.y * 8 + w) * 32;        // 0..2016
    const int uperm = (ln >> 1) & 3;                 // row = n0+ln
#pragma unroll 4
    for (int j = 0; j < 32; ++j) {
        float x = src[(size_t)(sK * 32 + j) * QD + n0 + ln];
        __nv_bfloat16 h = __float2bfloat16(x);
        __nv_bfloat16 l = __float2bfloat16(x - __bfloat162float(h));
        int u = j >> 3, e = j & 7;
        int pos = ln * 32 + ((u ^ uperm) << 3) + e;
        sh[w][pos] = h;
        sl[w][pos] = l;
    }
    __syncwarp();
    size_t rowbase = ((size_t)m * KSTAGES + sK) * QD + n0;  // staged row index
    uint4* dh = (uint4*)(g_Wst_hi + rowbase * 32);
    uint4* dl = (uint4*)(g_Wst_lo + rowbase * 32);
    const uint4* s4h = (const uint4*)sh[w];
    const uint4* s4l = (const uint4*)sl[w];
#pragma unroll
    for (int p = 0; p < 4; ++p) {
        dh[ln + 32 * p] = s4h[ln + 32 * p];
        dl[ln + 32 * p] = s4l[ln + 32 * p];
    }
}

// Input: in[r][k] * scale0[k] -> staged+swizzled set 0.
// Warp handles (stage sK, rows r0..r0+31). Lane=k elem, loop j=row.
__global__ void convert_input_staged(const float* __restrict__ in) {
    __shared__ __nv_bfloat16 sh[8][1024];
    __shared__ __nv_bfloat16 sl[8][1024];
    const int sK = blockIdx.x;
    const int w = threadIdx.x >> 5, ln = threadIdx.x & 31;
    const int r0 = (blockIdx.y * 8 + w) * 32;
    const float sc = g_scales[0][sK * 32 + ln];
    const int u = ln >> 3, e = ln & 7;
#pragma unroll 4
    for (int j = 0; j < 32; ++j) {
        float x = in[(size_t)(r0 + j) * QD + sK * 32 + ln] * sc;
        __nv_bfloat16 h = __float2bfloat16(x);
        __nv_bfloat16 l = __float2bfloat16(x - __bfloat162float(h));
        int pos = j * 32 + ((u ^ ((j >> 1) & 3)) << 3) + e;
        sh[w][pos] = h;
        sl[w][pos] = l;
    }
    __syncwarp();
    size_t rowbase = (size_t)sK * BATCH + r0;
    uint4* dh = (uint4*)(g_Ast_hi[0] + rowbase * 32);
    uint4* dl = (uint4*)(g_Ast_lo[0] + rowbase * 32);
    const uint4* s4h = (const uint4*)sh[w];
    const uint4* s4l = (const uint4*)sl[w];
#pragma unroll
    for (int p = 0; p < 4; ++p) {
        dh[ln + 32 * p] = s4h[ln + 32 * p];
        dl[ln + 32 * p] = s4l[ln + 32 * p];
    }
}

// ---------------------------------------------------------------------------
// tcgen05 GEMM, 256x256 CTA tile (two M=128 halves, D in 512 TMEM cols).
// 3-term bf16 split: Ahi*Bhi + Ahi*Blo + Alo*Bhi, fp32 accumulate.
// K-stage = 32 elems (64B rows, SW64), 64 iters, 3-stage bulk-copy pipeline.
// Warps 0-7: epilogue. Warp 8: bulk producer. Warp 9: MMA.
// mode 0/1: write staged+swizzled bf16 hi/lo of acc (*scaleNext if non-null).
// mode 2:   write fp32 rows to outF.
// ---------------------------------------------------------------------------
#define BM 256
#define BN 256
#define NSTAGE 3
#define TILE_B 16384                       // 256 rows x 64B
#define STAGE_B (4 * TILE_B)               // Ahi, Alo, Bhi, Blo = 64KB
#define K_ITERS KSTAGES                    // 64
// idesc: F32 acc, BF16 a/b, M=128, N=256
#define MMA_IDESC 0x8400490u

__global__ __launch_bounds__(320, 1)
void qgemm_kernel(const __nv_bfloat16* __restrict__ Ahi,
                  const __nv_bfloat16* __restrict__ Alo,
                  const __nv_bfloat16* __restrict__ Bhi,
                  const __nv_bfloat16* __restrict__ Blo,
                  float* __restrict__ outF,
                  __nv_bfloat16* __restrict__ outHi,
                  __nv_bfloat16* __restrict__ outLo,
                  const float* __restrict__ scaleNext,
                  int mode) {
#if HAS_TCGEN05
    extern __shared__ __align__(1024) char smem_dyn[];
    __shared__ __align__(8) unsigned long long s_bars[7];  // full[3] empty[3] done
    __shared__ uint32_t s_tmem;

    const int tid = threadIdx.x;
    const int wid = tid >> 5;
    const int lid = tid & 31;

    const uint32_t raw = smem_u32(smem_dyn);
    const uint32_t smem_base = (raw + 1023u) & ~1023u;
    char* smem_g = smem_dyn + (smem_base - raw);

    uint32_t bar_full[3], bar_empty[3], bar_done;
#pragma unroll
    for (int i = 0; i < 3; ++i) {
        bar_full[i]  = smem_u32(&s_bars[i]);
        bar_empty[i] = smem_u32(&s_bars[3 + i]);
    }
    bar_done = smem_u32(&s_bars[6]);

    if (tid == 0) {
#pragma unroll
        for (int i = 0; i < 3; ++i) {
            MBARRIER_INIT(bar_full[i], 1);
            MBARRIER_INIT(bar_empty[i], 1);
        }
        MBARRIER_INIT(bar_done, 1);
    }
    if (wid == 8) TCGEN05_ALLOC(smem_u32(&s_tmem), 512);
    __syncthreads();
    const uint32_t tmem_d = s_tmem;

    const int blockN = blockIdx.x * BN;
    const int blockM = blockIdx.y * BM;

    if (wid == 8) {
        // ---- producer: 4 x 16KB bulk copies per stage, single thread ----
        if (elect_one_pred()) {
            const char* pAh = (const char*)Ahi;
            const char* pAl = (const char*)Alo;
            const char* pBh = (const char*)Bhi;
            const char* pBl = (const char*)Blo;
            int s = 0, w = 0;
            for (int it = 0; it < K_ITERS; ++it) {
                if (it >= NSTAGE) MBARRIER_WAIT_PARITY(bar_empty[s], (w + 1) & 1);
                const uint32_t stage = smem_base + s * STAGE_B;
                const size_t aoff = ((size_t)it * BATCH + blockM) * 64;
                const size_t boff = ((size_t)it * QD + blockN) * 64;
                MBARRIER_EXPECT_TX(bar_full[s], STAGE_B);
                bulk_cp(stage,              pAh + aoff, TILE_B, bar_full[s]);
                bulk_cp(stage + TILE_B,     pAl + aoff, TILE_B, bar_full[s]);
                bulk_cp(stage + 2 * TILE_B, pBh + boff, TILE_B, bar_full[s]);
                bulk_cp(stage + 3 * TILE_B, pBl + boff, TILE_B, bar_full[s]);
                if (++s == NSTAGE) { s = 0; ++w; }
            }
        }
    } else if (wid == 9) {
        // ---- MMA warp: 12 dispatches per K-iter (2 halves x 3 terms x 2 chunks)
        int s = 0, w = 0;
        for (int it = 0; it < K_ITERS; ++it) {
            MBARRIER_WAIT_PARITY(bar_full[s], w & 1);
            const uint32_t stage = smem_base + s * STAGE_B;
            if (elect_one_pred()) {
                const uint64_t dBh = MAKE_DESC64(stage + 2 * TILE_B);
                const uint64_t dBl = MAKE_DESC64(stage + 3 * TILE_B);
#pragma unroll
                for (int h = 0; h < 2; ++h) {
                    const uint64_t dAh = MAKE_DESC64(stage + h * 8192);
                    const uint64_t dAl = MAKE_DESC64(stage + TILE_B + h * 8192);
                    const uint32_t d = tmem_d + h * 256;
#pragma unroll
                    for (int c = 0; c < 2; ++c) {
                        uint32_t en0 = (it == 0 && c == 0) ? 0u : 1u;
                        mma_f16_ss(d, dAh + 2 * c, dBh + 2 * c, MMA_IDESC, en0);
                        mma_f16_ss(d, dAh + 2 * c, dBl + 2 * c, MMA_IDESC, 1);
                        mma_f16_ss(d, dAl + 2 * c, dBh + 2 * c, MMA_IDESC, 1);
                    }
                }
                TCGEN05_COMMIT(bar_empty[s]);
            }
            if (++s == NSTAGE) { s = 0; ++w; }
        }
        if (elect_one_pred()) TCGEN05_COMMIT(bar_done);
    }

    __syncthreads();
    MBARRIER_WAIT_PARITY(bar_done, 0);
    TCGEN05_FENCE_AFTER();

    // ---- epilogue: warps 0-3 -> rows blockM..+127 (D cols 0-255),
    //                warps 4-7 -> rows blockM+128..+255 (D cols 256-511).
    if (wid < 8) {
        const int half = wid >> 2;
        const int rbase = blockM + half * 128 + (wid & 3) * 32;
        const int row = rbase + lid;
        const int uperm = (lid >> 1) & 3;  // rbase is a multiple of 32
        char* wsm = smem_g + wid * 4096;   // 2KB hi + 2KB lo scratch
#pragma unroll 1
        for (int ch = 0; ch < 8; ++ch) {
            uint32_t regs[32];
            TCGEN05_LD_32X32B_X32(regs, tmem_d + half * 256 + ch * 32);
            TCGEN05_WAIT_LD();
            const int c0 = blockN + ch * 32;
            if (mode == 2) {
                float* dst = outF + (size_t)row * QD + c0;
#pragma unroll
                for (int g = 0; g < 8; ++g)
                    *(float4*)(dst + g * 4) = make_float4(
                        __uint_as_float(regs[g * 4 + 0]), __uint_as_float(regs[g * 4 + 1]),
                        __uint_as_float(regs[g * 4 + 2]), __uint_as_float(regs[g * 4 + 3]));
            } else {
                uint32_t hp[16], lp[16];
#pragma unroll
                for (int q = 0; q < 16; ++q) {
                    float v0 = __uint_as_float(regs[2 * q]);
                    float v1 = __uint_as_float(regs[2 * q + 1]);
                    if (scaleNext) {
                        v0 *= scaleNext[c0 + 2 * q];
                        v1 *= scaleNext[c0 + 2 * q + 1];
                    }
                    __nv_bfloat16 h0 = __float2bfloat16(v0);
                    __nv_bfloat16 h1 = __float2bfloat16(v1);
                    __nv_bfloat16 l0 = __float2bfloat16(v0 - __bfloat162float(h0));
                    __nv_bfloat16 l1 = __float2bfloat16(v1 - __bfloat162float(h1));
                    hp[q] = (uint32_t)__bfloat16_as_ushort(h0) |
                            ((uint32_t)__bfloat16_as_ushort(h1) << 16);
                    lp[q] = (uint32_t)__bfloat16_as_ushort(l0) |
                            ((uint32_t)__bfloat16_as_ushort(l1) << 16);
                }
                // stage into smem, swizzled per output row (lid)
#pragma unroll
                for (int u = 0; u < 4; ++u) {
                    int up = (u ^ uperm) << 4;
                    *(uint4*)(wsm + lid * 64 + up) =
                        make_uint4(hp[4 * u], hp[4 * u + 1], hp[4 * u + 2], hp[4 * u + 3]);
                    *(uint4*)(wsm + 2048 + lid * 64 + up) =
                        make_uint4(lp[4 * u], lp[4 * u + 1], lp[4 * u + 2], lp[4 * u + 3]);
                }
                __syncwarp();
                // coalesced copy-out: rows rbase..rbase+31 of stage sK are 2KB contiguous
                const int sK = c0 >> 5;
                size_t rowbase = (size_t)sK * BATCH + rbase;
                uint4* dh = (uint4*)(outHi + rowbase * 32);
                uint4* dl = (uint4*)(outLo + rowbase * 32);
                const uint4* s4h = (const uint4*)wsm;
                const uint4* s4l = (const uint4*)(wsm + 2048);
#pragma unroll
                for (int p = 0; p < 4; ++p) {
                    dh[lid + 32 * p] = s4h[lid + 32 * p];
                    dl[lid + 32 * p] = s4l[lid + 32 * p];
                }
                __syncwarp();
            }
        }
        TCGEN05_FENCE_BEFORE();
    }

    __syncthreads();
    if (wid == 8) {
        TCGEN05_RELINQUISH();
        TCGEN05_DEALLOC(tmem_d, 512);
    }
#endif  // HAS_TCGEN05
}

// ---------------------------------------------------------------------------
// Launch
// ---------------------------------------------------------------------------
extern "C" void kernel_launch(void* const* d_in, const int* in_sizes, int n_in,
                              void* d_out, int out_size) {
    const float* input_state = (const float*)d_in[0];  // [B, QD]
    const float* angles      = (const float*)d_in[1];  // [L, QD, 3]
    const float* weights     = (const float*)d_in[2];  // [L, QD, QD]
    const float* meas_basis  = (const float*)d_in[3];  // [QD, QD]
    float* out = (float*)d_out;
    (void)in_sizes; (void)n_in; (void)out_size;

    __nv_bfloat16 *wh, *wl, *ah, *al;
    float* sc;
    cudaGetSymbolAddress((void**)&wh, g_Wst_hi);
    cudaGetSymbolAddress((void**)&wl, g_Wst_lo);
    cudaGetSymbolAddress((void**)&ah, g_Ast_hi);
    cudaGetSymbolAddress((void**)&al, g_Ast_lo);
    cudaGetSymbolAddress((void**)&sc, g_scales);

    const size_t dyn = NSTAGE * STAGE_B + 1024;
    cudaFuncSetAttribute(qgemm_kernel, cudaFuncAttributeMaxDynamicSharedMemorySize, dyn);

    compute_scales_kernel<<<(L_LAYERS * QD + 255) / 256, 256>>>(angles);
    convert_weights_staged<<<dim3(KSTAGES, QD / 256, NMAT), 256>>>(weights, meas_basis);
    convert_input_staged<<<dim3(KSTAGES, BATCH / 256), 256>>>(input_state);

    dim3 grid(QD / BN, BATCH / BM);  // (8, 16) = 128 CTAs, one wave
    const size_t MATSZ = (size_t)KSTAGES * QD * 32;
    const size_t STSZ  = (size_t)KSTAGES * BATCH * 32;

    for (int l = 0; l < L_LAYERS; ++l) {
        int rs = l & 1, ws = (l + 1) & 1;
        qgemm_kernel<<<grid, 320, dyn>>>(
            ah + (size_t)rs * STSZ, al + (size_t)rs * STSZ,
            wh + (size_t)l * MATSZ, wl + (size_t)l * MATSZ,
            nullptr,
            ah + (size_t)ws * STSZ, al + (size_t)ws * STSZ,
            (l < L_LAYERS - 1) ? (sc + (size_t)(l + 1) * QD) : nullptr,
            (l < L_LAYERS - 1) ? 0 : 1);
    }
    // final measurement GEMM -> fp32 out
    qgemm_kernel<<<grid, 320, dyn>>>(
        ah, al, wh + (size_t)16 * MATSZ, wl + (size_t)16 * MATSZ,
        out, nullptr, nullptr, nullptr, 2);
}

// round 5
// speedup vs baseline: 13.2300x; 1.0099x over previous
#include <cuda_runtime.h>
#include <cuda_bf16.h>
#include <cstdint>
#include <math.h>

#define L_LAYERS 16
#define QD 2048
#define BATCH 4096
#define NMAT 17  // 16 layers + measurement basis

// tcgen05 only exists on arch-specific targets (sm_103a); the harness also
// emits a generic compute_103 PTX pass, which must compile without it.
#if defined(__CUDA_ARCH_FEAT_SM103_ALL) || defined(__CUDA_ARCH_FEAT_SM100_ALL) || \
    (defined(__CUDA_ARCH_SPECIFIC__) && (__CUDA_ARCH_SPECIFIC__ >= 1000))
#define HAS_TCGEN05 1
#else
#define HAS_TCGEN05 0
#endif

// ---------------------------------------------------------------------------
// Device scratch. GEMM operands in K-staged, SW64-pre-swizzled layout:
//   [K/32 stages][rows][32 bf16]  -> per-stage CTA tile (256 rows x 64B = 16KB)
// is contiguous, fetched with one cp.async.bulk, landing exactly in the SW64
// layout the MMA smem descriptor expects.
// ---------------------------------------------------------------------------
#define KSTAGES (QD / 32)  // 64
__device__ __nv_bfloat16 g_Wst_hi[(size_t)NMAT * KSTAGES * QD * 32];
__device__ __nv_bfloat16 g_Wst_lo[(size_t)NMAT * KSTAGES * QD * 32];
__device__ __nv_bfloat16 g_Ast_hi[2][(size_t)KSTAGES * BATCH * 32];
__device__ __nv_bfloat16 g_Ast_lo[2][(size_t)KSTAGES * BATCH * 32];
__device__ float g_scales[L_LAYERS][QD];
__device__ int g_sync[NMAT][16];  // per (layer, M-group) arrival counters

// ---------------------------------------------------------------------------
// PTX helpers
// ---------------------------------------------------------------------------
__device__ __forceinline__ uint32_t smem_u32(const void* p) {
    uint32_t a;
    asm("{ .reg .u64 t; cvta.to.shared.u64 t, %1; cvt.u32.u64 %0, t; }"
        : "=r"(a) : "l"(p));
    return a;
}

__device__ __forceinline__ uint32_t elect_one_pred() {
    uint32_t pred;
    asm volatile(
        "{\n\t.reg .pred p;\n\telect.sync _|p, 0xFFFFFFFF;\n\t"
        "selp.b32 %0, 1, 0, p;\n\t}"
        : "=r"(pred));
    return pred;
}

#define MBARRIER_INIT(addr, count) \
    asm volatile("mbarrier.init.shared.b64 [%0], %1;" \
                 :: "r"((uint32_t)(addr)), "r"((uint32_t)(count)) : "memory")

#define MBARRIER_EXPECT_TX(addr, tx) \
    asm volatile("mbarrier.arrive.expect_tx.shared.b64 _, [%0], %1;" \
                 :: "r"((uint32_t)(addr)), "r"((uint32_t)(tx)) : "memory")

#define MBARRIER_WAIT_PARITY(mbar_smem_addr, phase_parity) do { \
    uint32_t _mbar = (uint32_t)(mbar_smem_addr); \
    uint32_t _parity = (uint32_t)(phase_parity); \
    uint32_t _done; \
    asm volatile( \
        "{\n\t.reg .pred p;\n\t" \
        "mbarrier.try_wait.parity.acquire.cta.shared::cta.b64 p, [%1], %2;\n\t" \
        "selp.b32 %0, 1, 0, p;\n\t}" \
        : "=r"(_done) : "r"(_mbar), "r"(_parity) : "memory"); \
    if (!_done) { \
        asm volatile( \
            "{\n\t.reg .pred P1;\n\t" \
            "WAIT_LOOP_%=:\n\t" \
            "mbarrier.try_wait.parity.acquire.cta.shared::cta.b64 P1, [%0], %1, 0x989680;\n\t" \
            "@P1 bra.uni WAIT_DONE_%=;\n\t" \
            "bra.uni WAIT_LOOP_%=;\n\t" \
            "WAIT_DONE_%=:\n\t}" \
            :: "r"(_mbar), "r"(_parity) : "memory"); \
    } \
} while (0)

__device__ __forceinline__ void bulk_cp(uint32_t dst, const void* src,
                                        uint32_t bytes, uint32_t mbar) {
    asm volatile(
        "cp.async.bulk.shared::cta.global.mbarrier::complete_tx::bytes "
        "[%0], [%1], %2, [%3];"
        :: "r"(dst), "l"(src), "r"(bytes), "r"(mbar) : "memory");
}

#if HAS_TCGEN05
#define TCGEN05_ALLOC(smem_result_addr, nCols) \
    asm volatile("tcgen05.alloc.cta_group::1.sync.aligned.shared::cta.b32 [%0], %1;" \
                 :: "r"((uint32_t)(smem_result_addr)), "r"((uint32_t)(nCols)) : "memory")
#define TCGEN05_DEALLOC(tmem_addr, nCols) \
    asm volatile("tcgen05.dealloc.cta_group::1.sync.aligned.b32 %0, %1;" \
                 :: "r"(tmem_addr), "r"((uint32_t)(nCols)))
#define TCGEN05_RELINQUISH() \
    asm volatile("tcgen05.relinquish_alloc_permit.cta_group::1.sync.aligned;")
#define TCGEN05_COMMIT(mbar) \
    asm volatile("tcgen05.commit.cta_group::1.mbarrier::arrive::one.shared::cluster.b64 [%0];" \
                 :: "r"((uint32_t)(mbar)) : "memory")
#define TCGEN05_FENCE_AFTER() \
    asm volatile("tcgen05.fence::after_thread_sync;" ::: "memory")
#define TCGEN05_FENCE_BEFORE() \
    asm volatile("tcgen05.fence::before_thread_sync;" ::: "memory")
#define TCGEN05_WAIT_LD() \
    asm volatile("tcgen05.wait::ld.sync.aligned;" ::: "memory")

#define TCGEN05_LD_32X32B_X32(r, tmem_addr) \
    asm volatile( \
        "tcgen05.ld.sync.aligned.32x32b.x32.b32 " \
        "{%0, %1, %2, %3, %4, %5, %6, %7, " \
        " %8, %9, %10, %11, %12, %13, %14, %15, " \
        " %16, %17, %18, %19, %20, %21, %22, %23, " \
        " %24, %25, %26, %27, %28, %29, %30, %31}, [%32];" \
        : "=r"((r)[0]),  "=r"((r)[1]),  "=r"((r)[2]),  "=r"((r)[3]), \
          "=r"((r)[4]),  "=r"((r)[5]),  "=r"((r)[6]),  "=r"((r)[7]), \
          "=r"((r)[8]),  "=r"((r)[9]),  "=r"((r)[10]), "=r"((r)[11]), \
          "=r"((r)[12]), "=r"((r)[13]), "=r"((r)[14]), "=r"((r)[15]), \
          "=r"((r)[16]), "=r"((r)[17]), "=r"((r)[18]), "=r"((r)[19]), \
          "=r"((r)[20]), "=r"((r)[21]), "=r"((r)[22]), "=r"((r)[23]), \
          "=r"((r)[24]), "=r"((r)[25]), "=r"((r)[26]), "=r"((r)[27]), \
          "=r"((r)[28]), "=r"((r)[29]), "=r"((r)[30]), "=r"((r)[31]) \
        : "r"(tmem_addr))

// SS-mode bf16 MMA, cg1
__device__ __forceinline__ void mma_f16_ss(uint32_t d, uint64_t da, uint64_t db,
                                           uint32_t idesc, uint32_t en) {
    asm volatile(
        "{\n\t.reg .pred p;\n\tsetp.ne.u32 p, %4, 0;\n\t"
        "tcgen05.mma.cta_group::1.kind::f16 [%0], %1, %2, %3, {%5,%5,%5,%5}, p;\n\t}"
        :: "r"(d), "l"(da), "l"(db), "r"(idesc), "r"(en), "r"(0u) : "memory");
}
#endif  // HAS_TCGEN05

// SW64 smem matrix descriptor: layout=4 (SW64), version=1, SBO=32, LBO=1.
static constexpr uint64_t DESC_SW64_BASE =
    (uint64_t(4) << 61) | (uint64_t(1) << 46) | (uint64_t(32) << 32) | (uint64_t(1) << 16);
#define MAKE_DESC64(a) (DESC_SW64_BASE | ((uint64_t)((a) >> 4) & 0x3FFF))

// ---------------------------------------------------------------------------
// Prep kernels (staged layout, SW64 swizzle pre-applied: unit u ^= (row>>1)&3)
// ---------------------------------------------------------------------------
__global__ void reset_sync_kernel() {
    int i = threadIdx.x;
    if (i < NMAT * 16) ((int*)g_sync)[i] = 0;
}

__global__ void compute_scales_kernel(const float* __restrict__ angles) {
    int idx = blockIdx.x * blockDim.x + threadIdx.x;
    if (idx < L_LAYERS * QD) {
        const float* a = angles + idx * 3;
        (&g_scales[0][0])[idx] = cosf(0.5f * a[0]) * cosf(0.5f * a[1]) * cosf(0.5f * a[2]);
    }
}

__global__ void convert_weights_staged(const float* __restrict__ weights,
                                       const float* __restrict__ meas) {
    __shared__ __nv_bfloat16 sh[8][1024];
    __shared__ __nv_bfloat16 sl[8][1024];
    const int m = blockIdx.z;
    const float* src = (m < L_LAYERS) ? (weights + (size_t)m * QD * QD) : meas;
    const int sK = blockIdx.x;
    const int w = threadIdx.x >> 5, ln = threadIdx.x & 31;
    const int n0 = (blockIdx.y * 8 + w) * 32;
    const int uperm = (ln >> 1) & 3;
#pragma unroll 4
    for (int j = 0; j < 32; ++j) {
        float x = src[(size_t)(sK * 32 + j) * QD + n0 + ln];
        __nv_bfloat16 h = __float2bfloat16(x);
        __nv_bfloat16 l = __float2bfloat16(x - __bfloat162float(h));
        int u = j >> 3, e = j & 7;
        int pos = ln * 32 + ((u ^ uperm) << 3) + e;
        sh[w][pos] = h;
        sl[w][pos] = l;
    }
    __syncwarp();
    size_t rowbase = ((size_t)m * KSTAGES + sK) * QD + n0;
    uint4* dh = (uint4*)(g_Wst_hi + rowbase * 32);
    uint4* dl = (uint4*)(g_Wst_lo + rowbase * 32);
    const uint4* s4h = (const uint4*)sh[w];
    const uint4* s4l = (const uint4*)sl[w];
#pragma unroll
    for (int p = 0; p < 4; ++p) {
        dh[ln + 32 * p] = s4h[ln + 32 * p];
        dl[ln + 32 * p] = s4l[ln + 32 * p];
    }
}

__global__ void convert_input_staged(const float* __restrict__ in) {
    __shared__ __nv_bfloat16 sh[8][1024];
    __shared__ __nv_bfloat16 sl[8][1024];
    const int sK = blockIdx.x;
    const int w = threadIdx.x >> 5, ln = threadIdx.x & 31;
    const int r0 = (blockIdx.y * 8 + w) * 32;
    const float sc = g_scales[0][sK * 32 + ln];
    const int u = ln >> 3, e = ln & 7;
#pragma unroll 4
    for (int j = 0; j < 32; ++j) {
        float x = in[(size_t)(r0 + j) * QD + sK * 32 + ln] * sc;
        __nv_bfloat16 h = __float2bfloat16(x);
        __nv_bfloat16 l = __float2bfloat16(x - __bfloat162float(h));
        int pos = j * 32 + ((u ^ ((j >> 1) & 3)) << 3) + e;
        sh[w][pos] = h;
        sl[w][pos] = l;
    }
    __syncwarp();
    size_t rowbase = (size_t)sK * BATCH + r0;
    uint4* dh = (uint4*)(g_Ast_hi[0] + rowbase * 32);
    uint4* dl = (uint4*)(g_Ast_lo[0] + rowbase * 32);
    const uint4* s4h = (const uint4*)sh[w];
    const uint4* s4l = (const uint4*)sl[w];
#pragma unroll
    for (int p = 0; p < 4; ++p) {
        dh[ln + 32 * p] = s4h[ln + 32 * p];
        dl[ln + 32 * p] = s4l[ln + 32 * p];
    }
}

// ---------------------------------------------------------------------------
// Persistent 17-layer chained GEMM. Grid (8,16) = 128 CTAs = one wave.
// Each CTA owns tile (blockM=256 rows, blockN=256 cols) for ALL layers.
// Layer dep is per M-group (8 CTAs): gmem release/acquire counter barrier.
// Warps 0-7: epilogue. Warp 8: bulk-copy producer. Warp 9: MMA.
// Continuous 3-stage smem pipeline across all 17*64 K-iterations.
// ---------------------------------------------------------------------------
#define BM 256
#define BN 256
#define NSTAGE 3
#define TILE_B 16384                       // 256 rows x 64B
#define STAGE_B (4 * TILE_B)               // Ahi, Alo, Bhi, Blo = 64KB
#define K_ITERS KSTAGES                    // 64
#define EPI_SMEM 32768                     // 8 warps x 4KB epilogue scratch
#define MMA_IDESC 0x8400490u               // F32 acc, BF16 a/b, M=128, N=256

__global__ __launch_bounds__(320, 1)
void qgemm_persistent(float* __restrict__ outF) {
#if HAS_TCGEN05
    extern __shared__ __align__(1024) char smem_dyn[];
    __shared__ __align__(8) unsigned long long s_bars[7];  // full[3] empty[3] done
    __shared__ uint32_t s_tmem;

    const int tid = threadIdx.x;
    const int wid = tid >> 5;
    const int lid = tid & 31;

    const uint32_t raw = smem_u32(smem_dyn);
    const uint32_t smem_base = (raw + 1023u) & ~1023u;
    char* smem_g = smem_dyn + (smem_base - raw);

    uint32_t bar_full[3], bar_empty[3], bar_done;
#pragma unroll
    for (int i = 0; i < 3; ++i) {
        bar_full[i]  = smem_u32(&s_bars[i]);
        bar_empty[i] = smem_u32(&s_bars[3 + i]);
    }
    bar_done = smem_u32(&s_bars[6]);

    if (tid == 0) {
#pragma unroll
        for (int i = 0; i < 3; ++i) {
            MBARRIER_INIT(bar_full[i], 1);
            MBARRIER_INIT(bar_empty[i], 1);
        }
        MBARRIER_INIT(bar_done, 1);
    }
    if (wid == 8) TCGEN05_ALLOC(smem_u32(&s_tmem), 512);
    __syncthreads();
    const uint32_t tmem_d = s_tmem;

    const int mi = blockIdx.y;
    const int blockN = blockIdx.x * BN;
    const int blockM = blockIdx.y * BM;
    const size_t MATB = (size_t)KSTAGES * QD * 64;  // bytes per weight matrix

    if (wid == 8) {
        // ---- producer: continuous loop over all layers' K stages -------
        if (elect_one_pred()) {
            int s = 0, w = 0;
            for (int it = 0; it < NMAT * K_ITERS; ++it) {
                const int l = it >> 6, k = it & 63;
                if (it >= NSTAGE) MBARRIER_WAIT_PARITY(bar_empty[s], (w + 1) & 1);
                const uint32_t stage = smem_base + s * STAGE_B;
                MBARRIER_EXPECT_TX(bar_full[s], STAGE_B);
                // B (weights): no cross-layer dependency -> issue immediately
                const size_t boff = (size_t)l * MATB + ((size_t)k * QD + blockN) * 64;
                bulk_cp(stage + 2 * TILE_B, (const char*)g_Wst_hi + boff, TILE_B, bar_full[s]);
                bulk_cp(stage + 3 * TILE_B, (const char*)g_Wst_lo + boff, TILE_B, bar_full[s]);
                // A (state): gated on the M-group barrier of the prev layer
                if (k == 0 && l > 0) {
                    const int* cnt = &g_sync[l - 1][mi];
                    int v;
                    do {
                        asm volatile("ld.acquire.gpu.global.b32 %0, [%1];"
                                     : "=r"(v) : "l"(cnt) : "memory");
                    } while (v < 8);
                    asm volatile("fence.proxy.async;" ::: "memory");
                }
                const int pb = l & 1;
                const size_t aoff = ((size_t)k * BATCH + blockM) * 64;
                bulk_cp(stage,          (const char*)g_Ast_hi[pb] + aoff, TILE_B, bar_full[s]);
                bulk_cp(stage + TILE_B, (const char*)g_Ast_lo[pb] + aoff, TILE_B, bar_full[s]);
                if (++s == NSTAGE) { s = 0; ++w; }
            }
        }
    } else if (wid == 9) {
        // ---- MMA warp ---------------------------------------------------
        int s = 0, w = 0;
        for (int l = 0; l < NMAT; ++l) {
            asm volatile("bar.sync 1, 288;" ::: "memory");  // TMEM handoff
            TCGEN05_FENCE_AFTER();
            for (int k = 0; k < K_ITERS; ++k) {
                MBARRIER_WAIT_PARITY(bar_full[s], w & 1);
                const uint32_t stage = smem_base + s * STAGE_B;
                if (elect_one_pred()) {
                    const uint64_t dBh = MAKE_DESC64(stage + 2 * TILE_B);
                    const uint64_t dBl = MAKE_DESC64(stage + 3 * TILE_B);
#pragma unroll
                    for (int h = 0; h < 2; ++h) {
                        const uint64_t dAh = MAKE_DESC64(stage + h * 8192);
                        const uint64_t dAl = MAKE_DESC64(stage + TILE_B + h * 8192);
                        const uint32_t d = tmem_d + h * 256;
#pragma unroll
                        for (int c = 0; c < 2; ++c) {
                            uint32_t en0 = (k == 0 && c == 0) ? 0u : 1u;
                            mma_f16_ss(d, dAh + 2 * c, dBh + 2 * c, MMA_IDESC, en0);
                            mma_f16_ss(d, dAh + 2 * c, dBl + 2 * c, MMA_IDESC, 1);
                            mma_f16_ss(d, dAl + 2 * c, dBh + 2 * c, MMA_IDESC, 1);
                        }
                    }
                    TCGEN05_COMMIT(bar_empty[s]);
                }
                if (++s == NSTAGE) { s = 0; ++w; }
            }
            if (elect_one_pred()) TCGEN05_COMMIT(bar_done);
        }
    } else {
        // ---- epilogue warps 0-7 ----------------------------------------
        const int half = wid >> 2;
        const int rbase = blockM + half * 128 + (wid & 3) * 32;
        const int row = rbase + lid;
        const int uperm = (lid >> 1) & 3;
        char* wsm = smem_g + NSTAGE * STAGE_B + wid * 4096;  // dedicated scratch
        for (int l = 0; l < NMAT; ++l) {
            asm volatile("bar.sync 1, 288;" ::: "memory");  // TMEM handoff
            MBARRIER_WAIT_PARITY(bar_done, l & 1);
            TCGEN05_FENCE_AFTER();
            const float* scaleNext = (l < L_LAYERS - 1) ? g_scales[l + 1] : nullptr;
            const int fpout = (l == NMAT - 1);
            const int wb = (l + 1) & 1;  // buffer next layer reads
            __nv_bfloat16* outHi = g_Ast_hi[wb];
            __nv_bfloat16* outLo = g_Ast_lo[wb];
#pragma unroll 1
            for (int ch = 0; ch < 8; ++ch) {
                uint32_t regs[32];
                TCGEN05_LD_32X32B_X32(regs, tmem_d + half * 256 + ch * 32);
                TCGEN05_WAIT_LD();
                const int c0 = blockN + ch * 32;
                if (fpout) {
                    float* dst = outF + (size_t)row * QD + c0;
#pragma unroll
                    for (int g = 0; g < 8; ++g)
                        *(float4*)(dst + g * 4) = make_float4(
                            __uint_as_float(regs[g * 4 + 0]), __uint_as_float(regs[g * 4 + 1]),
                            __uint_as_float(regs[g * 4 + 2]), __uint_as_float(regs[g * 4 + 3]));
                } else {
                    uint32_t hp[16], lp[16];
#pragma unroll
                    for (int q = 0; q < 16; ++q) {
                        float v0 = __uint_as_float(regs[2 * q]);
                        float v1 = __uint_as_float(regs[2 * q + 1]);
                        if (scaleNext) {
                            v0 *= scaleNext[c0 + 2 * q];
                            v1 *= scaleNext[c0 + 2 * q + 1];
                        }
                        __nv_bfloat16 h0 = __float2bfloat16(v0);
                        __nv_bfloat16 h1 = __float2bfloat16(v1);
                        __nv_bfloat16 l0 = __float2bfloat16(v0 - __bfloat162float(h0));
                        __nv_bfloat16 l1 = __float2bfloat16(v1 - __bfloat162float(h1));
                        hp[q] = (uint32_t)__bfloat16_as_ushort(h0) |
                                ((uint32_t)__bfloat16_as_ushort(h1) << 16);
                        lp[q] = (uint32_t)__bfloat16_as_ushort(l0) |
                                ((uint32_t)__bfloat16_as_ushort(l1) << 16);
                    }
#pragma unroll
                    for (int u = 0; u < 4; ++u) {
                        int up = (u ^ uperm) << 4;
                        *(uint4*)(wsm + lid * 64 + up) =
                            make_uint4(hp[4 * u], hp[4 * u + 1], hp[4 * u + 2], hp[4 * u + 3]);
                        *(uint4*)(wsm + 2048 + lid * 64 + up) =
                            make_uint4(lp[4 * u], lp[4 * u + 1], lp[4 * u + 2], lp[4 * u + 3]);
                    }
                    __syncwarp();
                    const int sK = c0 >> 5;
                    size_t rowbase = (size_t)sK * BATCH + rbase;
                    uint4* dh = (uint4*)(outHi + rowbase * 32);
                    uint4* dl = (uint4*)(outLo + rowbase * 32);
                    const uint4* s4h = (const uint4*)wsm;
                    const uint4* s4l = (const uint4*)(wsm + 2048);
#pragma unroll
                    for (int p = 0; p < 4; ++p) {
                        dh[lid + 32 * p] = s4h[lid + 32 * p];
                        dl[lid + 32 * p] = s4l[lid + 32 * p];
                    }
                    __syncwarp();
                }
            }
            TCGEN05_FENCE_BEFORE();
            asm volatile("bar.sync 2, 256;" ::: "memory");  // all epi warps done
            if (l < NMAT - 1 && wid == 0 && lid == 0) {
                __threadfence();
                asm volatile("red.release.gpu.global.add.s32 [%0], 1;"
                             :: "l"(&g_sync[l][mi]) : "memory");
            }
        }
    }

    __syncthreads();
    if (wid == 8) {
        TCGEN05_RELINQUISH();
        TCGEN05_DEALLOC(tmem_d, 512);
    }
#endif  // HAS_TCGEN05
}

// ---------------------------------------------------------------------------
// Launch
// ---------------------------------------------------------------------------
extern "C" void kernel_launch(void* const* d_in, const int* in_sizes, int n_in,
                              void* d_out, int out_size) {
    const float* input_state = (const float*)d_in[0];  // [B, QD]
    const float* angles      = (const float*)d_in[1];  // [L, QD, 3]
    const float* weights     = (const float*)d_in[2];  // [L, QD, QD]
    const float* meas_basis  = (const float*)d_in[3];  // [QD, QD]
    float* out = (float*)d_out;
    (void)in_sizes; (void)n_in; (void)out_size;

    const size_t dyn = NSTAGE * STAGE_B + EPI_SMEM + 1024;  // 225 KB
    cudaFuncSetAttribute(qgemm_persistent, cudaFuncAttributeMaxDynamicSharedMemorySize, dyn);

    reset_sync_kernel<<<1, 512>>>();
    compute_scales_kernel<<<(L_LAYERS * QD + 255) / 256, 256>>>(angles);
    convert_weights_staged<<<dim3(KSTAGES, QD / 256, NMAT), 256>>>(weights, meas_basis);
    convert_input_staged<<<dim3(KSTAGES, BATCH / 256), 256>>>(input_state);

    dim3 grid(QD / BN, BATCH / BM);  // (8, 16) = 128 CTAs, one wave
    qgemm_persistent<<<grid, 320, dyn>>>(out);
}